// round 13
// baseline (speedup 1.0000x reference)
#include <cuda_runtime.h>
#include <cuda_fp16.h>
#include <cstdint>

// Problem: B=16384, D=1024, T=512
// out[b,t] = (x@Wb + bb) + cumsum_t( relu(x@Wh^T + bh) )
// FP16 HMMA. BM=64 / 256 threads / grid=256 -> 2 CTAs per SM (independent
// barrier domains; r11 was latency/barrier-bound at 1 CTA/SM). Warp tile
// 32x64 (2x4 warps). 2-stage cp.async B pipeline (wait->sync->issue order
// keeps the shallow ring race-free). In-loop A convert interleaved between
// MMA kk-blocks (r11 scheme). Fused carry-scan epilogue.

#define D_DIM 1024
#define T_DIM 512
#define BM    64
#define BN    256
#define BK    64
#define THREADS 256
#define HPITCH 68             // floats, per 64-col quarter

// ---- global scratch ----
__device__ __half g_wh[T_DIM * D_DIM];

// ---- smem layout (bytes) ----
#define SM_BH    0                       // 512 f (2048)
#define SM_WB    2048                    // 1024 f (4096)
#define SM_CARRY 6144                    // 64 f (256)
#define SM_STOT0 6400                    // 64 f (256)
#define SM_STOT1 6656                    // 64 f (256)
#define SM_RED   6912                    // 256 f (1024)
#define SM_CONV  8192                    // 2 groups x 2 x 4096 = 16384
#define SM_BSTG  24576                   // 2 stages x 32768 = 65536
#define SM_HAZ   90112                   // 64*68*4 = 17408
#define SMEM_TOTAL 107520

// ---------------- helpers ----------------
__device__ __forceinline__ uint32_t smem_u32(const void* p) {
    uint32_t a;
    asm("{ .reg .u64 t; cvta.to.shared.u64 t, %1; cvt.u32.u64 %0, t; }" : "=r"(a) : "l"(p));
    return a;
}
__device__ __forceinline__ uint32_t swz128(uint32_t o) { return o ^ ((o >> 3) & 0x70); }

#define CP16(dst, src) \
    asm volatile("cp.async.cg.shared.global [%0], [%1], 16;" :: "r"(dst), "l"(src) : "memory")
#define CP_COMMIT() asm volatile("cp.async.commit_group;" ::: "memory")
#define CP_WAIT0()  asm volatile("cp.async.wait_group 0;" ::: "memory")
#define GROUP_BAR(id) \
    asm volatile("bar.sync %0, 128;" :: "r"(id) : "memory")

__device__ __forceinline__ void ldsm4(uint32_t* r, uint32_t addr) {
    asm volatile("ldmatrix.sync.aligned.m8n8.x4.shared.b16 {%0,%1,%2,%3}, [%4];"
                 : "=r"(r[0]), "=r"(r[1]), "=r"(r[2]), "=r"(r[3]) : "r"(addr));
}
__device__ __forceinline__ void mma16816(float* d, const uint32_t* a, const uint32_t* b) {
    asm volatile(
        "mma.sync.aligned.m16n8k16.row.col.f32.f16.f16.f32 "
        "{%0,%1,%2,%3}, {%4,%5,%6,%7}, {%8,%9}, {%0,%1,%2,%3};"
        : "+f"(d[0]), "+f"(d[1]), "+f"(d[2]), "+f"(d[3])
        : "r"(a[0]), "r"(a[1]), "r"(a[2]), "r"(a[3]), "r"(b[0]), "r"(b[1]));
}
__device__ __forceinline__ uint32_t pk2h(float a, float b) {
    __half2 h = __floats2half2_rn(a, b);
    return *(uint32_t*)&h;
}

// -------- prologue: convert Wh to fp16 --------
__global__ __launch_bounds__(256)
void wh_conv_kernel(const float* __restrict__ Wh) {
    int i = (blockIdx.x * 256 + threadIdx.x) * 4;
    float4 w = *(const float4*)(Wh + i);
    uint2 v = { pk2h(w.x, w.y), pk2h(w.z, w.w) };
    *(uint2*)((char*)g_wh + (size_t)i * 2) = v;
}

// -------- main fused kernel --------
__global__ __launch_bounds__(THREADS, 2)
void fused_kernel(const float* __restrict__ X,
                  const float* __restrict__ bh,
                  const float* __restrict__ Wb,
                  const float* __restrict__ bb,
                  float* __restrict__ out) {
    extern __shared__ char sm[];
    const uint32_t su = smem_u32(sm);
    const int tid = threadIdx.x;
    const int lane = tid & 31;
    const int wid = tid >> 5;
    const int g = wid >> 2;         // warprow group 0..1 -> m *32
    const int warpcol = wid & 3;    // 0..3 -> n *64
    const int bm = blockIdx.x * BM;

    float* sbh = (float*)(sm + SM_BH);
    float* swb = (float*)(sm + SM_WB);
    float* scarry = (float*)(sm + SM_CARRY);
    float* stot0 = (float*)(sm + SM_STOT0);
    float* stot1 = (float*)(sm + SM_STOT1);
    float* sred = (float*)(sm + SM_RED);
    float* shz = (float*)(sm + SM_HAZ);       // [64][HPITCH]

    for (int i = tid; i < T_DIM; i += THREADS) sbh[i] = bh[i];
    for (int i = tid; i < D_DIM; i += THREADS) swb[i] = Wb[i];
    const float bbv = bb[0];
    __syncthreads();

    // ---- conversion mapping: group g owns A rows 32g..32g+31 ----
    const int gt = tid & 127;
    const int cr = gt >> 2;          // row in group (0..31)
    const int cq = gt & 3;           // 16-col quarter of the 64-col chunk
    const float* xrow = X + (size_t)(bm + 32 * g + cr) * D_DIM + cq * 16;
    const uint32_t cdst0 = (uint32_t)cr * 128 + (((uint32_t)(2 * cq) << 4) ^ (((uint32_t)cr & 7) << 4));
    const uint32_t convg = SM_CONV + g * 8192;

    // ---- ldsm fragment address components (128B rows, SW128) ----
    const uint32_t xmask = ((uint32_t)lane & 7) << 4;
    const uint32_t a_rowoff = ((uint32_t)lane & 15) * 128;
    const uint32_t a_l16 = (((uint32_t)lane >> 4) & 1) * 16;
    const uint32_t b_rowoff = ((uint32_t)(warpcol * 64 + (lane & 7) + ((lane >> 4) & 1) * 8)) * 128;
    const uint32_t b_l16 = (((uint32_t)lane >> 3) & 1) * 16;

    float v[16];
    float pbase = 0.0f;
    float acc[64];
#pragma unroll
    for (int j = 0; j < 64; j++) acc[j] = 0.0f;

    #define COMPUTE_KK(kk)                                                     \
    {                                                                          \
        const uint32_t akb = ((uint32_t)(kk) * 32 + a_l16) ^ xmask;            \
        const uint32_t bkb = ((uint32_t)(kk) * 32 + b_l16) ^ xmask;            \
        uint32_t bfr[4][4];                                                    \
        _Pragma("unroll")                                                      \
        for (int p = 0; p < 4; p++)                                            \
            ldsm4(bfr[p], sB + b_rowoff + p * 2048 + bkb);                     \
        _Pragma("unroll")                                                      \
        for (int mt = 0; mt < 2; mt++) {                                       \
            uint32_t af[4];                                                    \
            ldsm4(af, aB + a_rowoff + mt * 2048 + akb);                        \
            _Pragma("unroll")                                                  \
            for (int nt = 0; nt < 8; nt++) {                                   \
                float* d = acc + (mt * 8 + nt) * 4;                            \
                mma16816(d, af, &bfr[nt >> 1][(nt & 1) * 2]);                  \
            }                                                                  \
        }                                                                      \
    }

    // B issue for chunk ch into stage ch&1 (2048 segs, 8/thread: row==tid)
    #define ISSUE_B(ch)                                                        \
    {                                                                          \
        const int nci = (ch) >> 4;                                             \
        const int k0 = ((ch) & 15) * BK;                                       \
        const uint32_t sBo = su + SM_BSTG + ((ch) & 1) * 32768;                \
        const size_t gbase = ((size_t)(nci * BN + tid) * D_DIM + k0) * 2;      \
        _Pragma("unroll")                                                      \
        for (int q = 0; q < 8; q++)                                            \
            CP16(sBo + swz128((uint32_t)(tid * 128 + q * 16)),                 \
                 (const char*)g_wh + gbase + q * 16);                          \
        CP_COMMIT();                                                           \
    }

    // ---- prologue ----
    {
        ISSUE_B(0)
        // LDG chunk 0
        *(float4*)(v + 0)  = *(const float4*)(xrow + 0);
        *(float4*)(v + 4)  = *(const float4*)(xrow + 4);
        *(float4*)(v + 8)  = *(const float4*)(xrow + 8);
        *(float4*)(v + 12) = *(const float4*)(xrow + 12);
        // convert chunk 0 -> buf 0 (+pbase)
        const float* wbp = swb + cq * 16;
#pragma unroll
        for (int j = 0; j < 16; j++) pbase = fmaf(v[j], wbp[j], pbase);
        uint4 h0 = { pk2h(v[0], v[1]),  pk2h(v[2], v[3]),
                     pk2h(v[4], v[5]),  pk2h(v[6], v[7]) };
        uint4 h1 = { pk2h(v[8], v[9]),  pk2h(v[10], v[11]),
                     pk2h(v[12], v[13]), pk2h(v[14], v[15]) };
        *(uint4*)(sm + convg + cdst0)        = h0;
        *(uint4*)(sm + convg + (cdst0 ^ 16)) = h1;
        // LDG chunk 1
        const float* xp = xrow + BK;
        *(float4*)(v + 0)  = *(const float4*)(xp + 0);
        *(float4*)(v + 4)  = *(const float4*)(xp + 4);
        *(float4*)(v + 8)  = *(const float4*)(xp + 8);
        *(float4*)(v + 12) = *(const float4*)(xp + 12);
        GROUP_BAR(g + 1);
    }

    // ---- main loop: iters 1..32, compute chunk c = i-1 ----
#pragma unroll 1
    for (int i = 1; i <= 32; i++) {
        const int c = i - 1;
        const int cc = i;                 // chunk being converted this iter

        CP_WAIT0();                       // B_{c} landed
        __syncthreads();                  // all warps done reading stage i&1 (chunk i-2)
        if (i < 32) ISSUE_B(i)            // overwrite stage i&1 under compute of c

        const uint32_t aB = su + convg + (c & 1) * 4096;
        const uint32_t sB = su + SM_BSTG + (c & 1) * 32768;
        const bool docv = (cc < 32);
        const bool dobase = (cc < 16);

        COMPUTE_KK(0)
        if (docv) {
            if (dobase) {
                const float* wbp = swb + cc * BK + cq * 16;
#pragma unroll
                for (int j = 0; j < 8; j++) pbase = fmaf(v[j], wbp[j], pbase);
            }
            uint4 h0 = { pk2h(v[0], v[1]), pk2h(v[2], v[3]),
                         pk2h(v[4], v[5]), pk2h(v[6], v[7]) };
            *(uint4*)(sm + convg + (cc & 1) * 4096 + cdst0) = h0;
        }
        COMPUTE_KK(1)
        if (docv) {
            if (dobase) {
                const float* wbp = swb + cc * BK + cq * 16;
#pragma unroll
                for (int j = 8; j < 16; j++) pbase = fmaf(v[j], wbp[j], pbase);
            }
            uint4 h1 = { pk2h(v[8], v[9]),  pk2h(v[10], v[11]),
                         pk2h(v[12], v[13]), pk2h(v[14], v[15]) };
            *(uint4*)(sm + convg + (cc & 1) * 4096 + (cdst0 ^ 16)) = h1;
        }
        COMPUTE_KK(2)
        if (i < 31) {
            const float* xp = xrow + ((i + 1) & 15) * BK;
            *(float4*)(v + 0)  = *(const float4*)(xp + 0);
            *(float4*)(v + 4)  = *(const float4*)(xp + 4);
            *(float4*)(v + 8)  = *(const float4*)(xp + 8);
            *(float4*)(v + 12) = *(const float4*)(xp + 12);
        }
        COMPUTE_KK(3)

        GROUP_BAR(g + 1);

        // ---- nc boundary: epilogue ----
        if (c == 15 || c == 31) {
            const int nc = c >> 4;
            if (nc == 0) {
                __syncthreads();
                sred[tid] = pbase;
                __syncthreads();
                if (tid < BM) {
                    int o = (tid >> 5) * 128 + (tid & 31) * 4;
                    scarry[tid] = sred[o] + sred[o + 1] + sred[o + 2] + sred[o + 3] + bbv;
                }
            }
#pragma unroll 1
            for (int quarter = 0; quarter < 4; quarter++) {
                __syncthreads();
                // the 2 warps with warpcol==quarter write hazards (+bh, relu)
                if (warpcol == quarter) {
#pragma unroll
                    for (int mt = 0; mt < 2; mt++)
#pragma unroll
                        for (int nt = 0; nt < 8; nt++) {
                            const float* d = acc + (mt * 8 + nt) * 4;
                            int r0 = g * 32 + mt * 16 + (lane >> 2);
                            int c0 = nt * 8 + 2 * (lane & 3);
                            int cg = nc * BN + quarter * 64 + c0;
                            float b0 = sbh[cg], b1 = sbh[cg + 1];
                            shz[r0 * HPITCH + c0]           = fmaxf(d[0] + b0, 0.0f);
                            shz[r0 * HPITCH + c0 + 1]       = fmaxf(d[1] + b1, 0.0f);
                            shz[(r0 + 8) * HPITCH + c0]     = fmaxf(d[2] + b0, 0.0f);
                            shz[(r0 + 8) * HPITCH + c0 + 1] = fmaxf(d[3] + b1, 0.0f);
                        }
                }
                __syncthreads();
                // split scan: 2 threads/row, 32 cols each
                if (tid < 128) {
                    int r = tid >> 1, hh = tid & 1;
                    float run = 0.0f;
                    float4* rp = (float4*)(shz + r * HPITCH + hh * 32);
#pragma unroll
                    for (int j = 0; j < 8; j++) {
                        float4 v4 = rp[j];
                        v4.x += run; v4.y += v4.x; v4.z += v4.y; v4.w += v4.z;
                        run = v4.w;
                        rp[j] = v4;
                    }
                    if (hh == 0) stot0[r] = run; else stot1[r] = run;
                }
                __syncthreads();
                // coalesced store (+carry, +half fixup)
#pragma unroll
                for (int it = 0; it < 4; it++) {
                    int idx = it * 256 + tid;          // 1024 float4
                    int row = idx >> 4;
                    int c4 = (idx & 15) * 4;
                    float add = scarry[row] + ((c4 & 32) ? stot0[row] : 0.0f);
                    const float* rp = shz + row * HPITCH + c4;
                    float4 o = { rp[0] + add, rp[1] + add, rp[2] + add, rp[3] + add };
                    *(float4*)(out + (size_t)(bm + row) * T_DIM + nc * BN + quarter * 64 + c4) = o;
                }
                __syncthreads();
                if (tid < BM) scarry[tid] += stot0[tid] + stot1[tid];
            }
            if (nc == 0) {
#pragma unroll
                for (int j = 0; j < 64; j++) acc[j] = 0.0f;
            }
        }
    }
    #undef COMPUTE_KK
    #undef ISSUE_B
}

extern "C" void kernel_launch(void* const* d_in, const int* in_sizes, int n_in,
                              void* d_out, int out_size) {
    const float* x  = (const float*)d_in[0];
    const float* Wh = (const float*)d_in[1];
    const float* bh = (const float*)d_in[2];
    const float* Wb = (const float*)d_in[3];
    const float* bb = (const float*)d_in[4];
    float* out = (float*)d_out;

    const int B = in_sizes[0] / D_DIM;   // 16384

    cudaFuncSetAttribute(fused_kernel,
                         cudaFuncAttributeMaxDynamicSharedMemorySize, SMEM_TOTAL);

    wh_conv_kernel<<<(T_DIM * D_DIM) / 1024, 256>>>(Wh);
    fused_kernel<<<B / BM, THREADS, SMEM_TOTAL>>>(x, bh, Wb, bb, out);
}